// round 7
// baseline (speedup 1.0000x reference)
#include <cuda_runtime.h>
#include <stdint.h>

#define NN2  361
#define MM   361
#define NT   256
#define BLOOM_WORDS 1024          // 4 KB = 32768 bits, k=2
#define MAXST 256
#define MAXG  64

__device__ __forceinline__ void bloom_bits(int v, unsigned &b1, unsigned &b2) {
    b1 = (((unsigned)v) * 0x9E3779B1u) >> 17;   // 15 bits
    b2 = (((unsigned)v) * 0x85EBCA6Bu) >> 17;   // 15 bits
}

__global__ __launch_bounds__(NT)
void superko_kernel(const int* __restrict__ ZposT,           // [3, N2]
                    const int* __restrict__ current_player,  // [B]
                    const int* __restrict__ current_hash,    // [B]
                    const int* __restrict__ hash_history,    // [B, M]
                    const int* __restrict__ move_count,      // [B]
                    const int* __restrict__ legal,           // [B, N2] bool(4B)
                    const int* __restrict__ sidx,            // [K]
                    const int* __restrict__ sptr,            // [R+1]
                    const int* __restrict__ gptr,            // [B+1]
                    const int* __restrict__ cap,             // [B, N2, 4]
                    float* __restrict__ out)                 // [B, N2] bool-as-f32
{
    __shared__ __align__(16) unsigned bloom[BLOOM_WORDS];
    __shared__ __align__(16) int szpos[3 * NN2 + 1];   // 1083 ints (+pad)
    __shared__ int shist[MM];
    __shared__ int gxor[MAXG];
    __shared__ int sdelta[MAXST];                      // general-CSR fallback only

    const int b   = blockIdx.x;
    const int tid = threadIdx.x;

    // ---------------- phase 0: fire all global loads ----------------
    const int player = __ldg(&current_player[b]);
    int mc           = __ldg(&move_count[b]);
    const int ch     = __ldg(&current_hash[b]);
    if (mc > MM) mc = MM;
    if (mc < 0)  mc = 0;

    const int4* cap4 = (const int4*)(cap + (long long)b * NN2 * 4);
    const int*  lg   = legal + (long long)b * NN2;
    const int*  hist = hash_history + (long long)b * MM;

    const int j0 = tid, j1 = tid + NT;
    const bool has1 = (j1 < NN2);

    int4 c4_0 = cap4[j0];
    int  lg_0 = lg[j0];
    int4 c4_1 = make_int4(-1, -1, -1, -1);
    int  lg_1 = 0;
    if (has1) { c4_1 = cap4[j1]; lg_1 = lg[j1]; }

    int hv0 = hist[j0];
    int hv1 = has1 ? hist[j1] : 0;

    // stage ZposT (1083 ints) into SMEM with coalesced int4 loads
    {
        const int4* z4 = (const int4*)ZposT;
        int4* s4 = (int4*)szpos;
        s4[tid] = z4[tid];                         // ints 0..1023
        if (tid < 14) s4[NT + tid] = z4[NT + tid]; // ints 1024..1079
        if (tid < 3)  szpos[1080 + tid] = ZposT[1080 + tid];
    }

    // bloom init (one STS.128 per thread)
    ((int4*)bloom)[tid] = make_int4(0, 0, 0, 0);

    // stage history to SMEM (for rare exact verification)
    shist[j0] = hv0;
    if (has1) shist[j1] = hv1;

    // CSR scalar chain (broadcast loads; L1-hot after first warp)
    const int gstart = gptr[b];
    int ng = gptr[b + 1] - gstart;
    if (ng < 0) ng = 0;
    if (ng > MAXG) ng = MAXG;
    const int sbase = sptr[gstart];
    int nst = sptr[gstart + ng] - sbase;
    if (nst < 0) nst = 0;

    bool uniform = (nst == ng * 16) && (nst <= MAXST) && ((nst & 31) == 0);
    for (int g = 1; g < ng && uniform; ++g)
        uniform = (sptr[gstart + g] == sbase + 16 * g);

    int c_reg = 0;
    if (tid < nst && tid < MAXST) c_reg = sidx[sbase + tid];

    __syncthreads();   // barrier 1: szpos/bloom/shist ready

    // ---------------- phase 1: bloom inserts + group XORs ----------------
    if (j0 < mc) {
        unsigned b1, b2; bloom_bits(hv0, b1, b2);
        atomicOr(&bloom[b1 >> 5], 1u << (b1 & 31));
        atomicOr(&bloom[b2 >> 5], 1u << (b2 & 31));
    }
    if (j1 < mc) {
        unsigned b1, b2; bloom_bits(hv1, b1, b2);
        atomicOr(&bloom[b1 >> 5], 1u << (b1 & 31));
        atomicOr(&bloom[b2 >> 5], 1u << (b2 & 31));
    }

    const int opp_row = (2 - player) * NN2;   // opponent color row base
    if (uniform) {
        // stones 16-per-group, thread s = stone s; butterfly XOR within 16 lanes
        if (tid < nst) {
            int d = szpos[c_reg] ^ szpos[opp_row + c_reg];
            d ^= __shfl_xor_sync(0xffffffffu, d, 8);
            d ^= __shfl_xor_sync(0xffffffffu, d, 4);
            d ^= __shfl_xor_sync(0xffffffffu, d, 2);
            d ^= __shfl_xor_sync(0xffffffffu, d, 1);
            if ((tid & 15) == 0) gxor[tid >> 4] = d;
        }
    } else {
        // general CSR fallback (not taken on this dataset)
        for (int s = tid; s < nst && s < MAXST; s += NT) {
            int c = (s == tid) ? c_reg : sidx[sbase + s];
            sdelta[s] = szpos[c] ^ szpos[opp_row + c];
        }
        __syncthreads();
        if (tid < ng) {
            int s0 = sptr[gstart + tid] - sbase;
            int s1 = sptr[gstart + tid + 1] - sbase;
            if (s0 < 0) s0 = 0;
            if (s1 > nst) s1 = nst;
            if (s1 > MAXST) s1 = MAXST;
            int x = 0;
            for (int s = s0; s < s1; ++s) x ^= sdelta[s];
            gxor[tid] = x;
        }
    }

    __syncthreads();   // barrier 2: bloom + gxor final

    // ---------------- phase 2: candidate + bloom probe + output ----------------
    const int cur_row = (1 + player) * NN2;
    float* ob = out + (long long)b * NN2;

    {
        int cd = 0;
        if (c4_0.x >= 0) cd ^= gxor[c4_0.x];
        if (c4_0.y >= 0) cd ^= gxor[c4_0.y];
        if (c4_0.z >= 0) cd ^= gxor[c4_0.z];
        if (c4_0.w >= 0) cd ^= gxor[c4_0.w];
        int cand = ch ^ (szpos[j0] ^ szpos[cur_row + j0]) ^ cd;

        unsigned b1, b2; bloom_bits(cand, b1, b2);
        unsigned w1 = bloom[b1 >> 5];
        unsigned w2 = bloom[b2 >> 5];
        bool found = false;
        if ((w1 >> (b1 & 31)) & (w2 >> (b2 & 31)) & 1u) {
            for (int t = 0; t < mc; ++t)
                if (shist[t] == cand) { found = true; break; }
        }
        ob[j0] = (lg_0 != 0 && !found) ? 1.0f : 0.0f;
    }
    if (has1) {
        int cd = 0;
        if (c4_1.x >= 0) cd ^= gxor[c4_1.x];
        if (c4_1.y >= 0) cd ^= gxor[c4_1.y];
        if (c4_1.z >= 0) cd ^= gxor[c4_1.z];
        if (c4_1.w >= 0) cd ^= gxor[c4_1.w];
        int cand = ch ^ (szpos[j1] ^ szpos[cur_row + j1]) ^ cd;

        unsigned b1, b2; bloom_bits(cand, b1, b2);
        unsigned w1 = bloom[b1 >> 5];
        unsigned w2 = bloom[b2 >> 5];
        bool found = false;
        if ((w1 >> (b1 & 31)) & (w2 >> (b2 & 31)) & 1u) {
            for (int t = 0; t < mc; ++t)
                if (shist[t] == cand) { found = true; break; }
        }
        ob[j1] = (lg_1 != 0 && !found) ? 1.0f : 0.0f;
    }
}

extern "C" void kernel_launch(void* const* d_in, const int* in_sizes, int n_in,
                              void* d_out, int out_size) {
    const int* ZposT        = (const int*)d_in[0];
    const int* cur_player   = (const int*)d_in[1];
    const int* cur_hash     = (const int*)d_in[2];
    const int* hash_hist    = (const int*)d_in[3];
    const int* mv_count     = (const int*)d_in[4];
    const int* lg           = (const int*)d_in[5];
    const int* sidx         = (const int*)d_in[6];
    const int* sptr         = (const int*)d_in[7];
    const int* gptr         = (const int*)d_in[8];
    const int* cap          = (const int*)d_in[9];
    // d_in[10] = scale (unused)

    float* out = (float*)d_out;
    const int B = in_sizes[8] - 1;   // gptr has B+1 entries

    superko_kernel<<<B, NT>>>(ZposT, cur_player, cur_hash, hash_hist,
                              mv_count, lg, sidx, sptr, gptr, cap, out);
}

// round 8
// speedup vs baseline: 1.3200x; 1.3200x over previous
#include <cuda_runtime.h>
#include <stdint.h>

#define NN2  361
#define MM   361
#define HALF 181            // cells per half-board CTA (2*181 >= 361)
#define HASH_SLOTS 1024
#define HASH_MASK  1023
#define NT   256
#define MAXG  64
#define MAXST 256

__device__ __forceinline__ unsigned hash_fn(int v) {
    return (((unsigned)v) * 2654435761u) >> 22;   // top 10 bits -> [0,1024)
}

__device__ __forceinline__ void hset_insert(int* hset, int v) {
    unsigned h = hash_fn(v) & HASH_MASK;
    while (true) {
        int prev = atomicCAS(&hset[h], -1, v);
        if (prev == -1 || prev == v) break;
        h = (h + 1) & HASH_MASK;
    }
}

__global__ __launch_bounds__(NT)
void superko_kernel(const int* __restrict__ ZposT,           // [3, N2]
                    const int* __restrict__ current_player,  // [B]
                    const int* __restrict__ current_hash,    // [B]
                    const int* __restrict__ hash_history,    // [B, M]
                    const int* __restrict__ move_count,      // [B]
                    const int* __restrict__ legal,           // [B, N2] bool(4B)
                    const int* __restrict__ sidx,            // [K]
                    const int* __restrict__ sptr,            // [R+1]
                    const int* __restrict__ gptr,            // [B+1]
                    const int* __restrict__ cap,             // [B, N2, 4]
                    float* __restrict__ out)                 // [B, N2] bool-as-f32
{
    __shared__ int hset[HASH_SLOTS];
    __shared__ int gxor[MAXG];
    __shared__ int sdelta[MAXST];    // general-CSR fallback only

    const int b    = blockIdx.x >> 1;        // board
    const int half = blockIdx.x & 1;         // 0: cells [0,181), 1: cells [181,361)
    const int tid  = threadIdx.x;

    // ---------------- phase 0: fire all independent loads ----------------
    const int player = __ldg(&current_player[b]);
    int mc           = __ldg(&move_count[b]);
    const int ch     = __ldg(&current_hash[b]);
    if (mc > MM) mc = MM;
    if (mc < 0)  mc = 0;

    const int j = half * HALF + tid;               // this thread's cell
    const bool hasc = (tid < HALF) && (j < NN2);

    // cell data (registers only)
    int4 c4 = make_int4(-1, -1, -1, -1);
    int  lgv = 0, ze = 0, zb = 0, zw = 0;
    if (hasc) {
        c4  = ((const int4*)(cap + (long long)b * NN2 * 4))[j];
        lgv = legal[(long long)b * NN2 + j];
        ze  = __ldg(&ZposT[j]);
        zb  = __ldg(&ZposT[NN2 + j]);
        zw  = __ldg(&ZposT[2 * NN2 + j]);
    }

    // history prefetch (full history in every CTA: any cell can match any entry)
    const int* hist = hash_history + (long long)b * MM;
    int hv0 = hist[tid];
    int hv1 = (tid + NT < MM) ? hist[tid + NT] : 0;

    // CSR scalars (broadcast; L1/L2-hot)
    const int gstart = gptr[b];
    int ng = gptr[b + 1] - gstart;
    if (ng < 0) ng = 0;
    if (ng > MAXG) ng = MAXG;
    const int sbase = sptr[gstart];
    int nst = sptr[gstart + ng] - sbase;
    if (nst < 0) nst = 0;

    bool uniform = (nst == ng * 16) && (nst <= MAXST) && ((nst & 31) == 0);
    for (int g = 1; g < ng && uniform; ++g)
        uniform = (sptr[gstart + g] == sbase + 16 * g);

    // speculative stone gather (fast path): stone tid, both colors
    int sd = 0;
    if (tid < nst && tid < MAXST) {
        int c = sidx[sbase + tid];
        int sze = __ldg(&ZposT[c]);
        int szo = (player == 0) ? __ldg(&ZposT[2 * NN2 + c]) : __ldg(&ZposT[NN2 + c]);
        sd = sze ^ szo;
    }

    // hash set init: exactly one STS.128 per thread
    ((int4*)hset)[tid] = make_int4(-1, -1, -1, -1);

    // fast-path group XOR: 16-lane butterfly (warps 0-3)
    if (uniform && tid < nst) {
        int d = sd;
        d ^= __shfl_xor_sync(0xffffffffu, d, 8);
        d ^= __shfl_xor_sync(0xffffffffu, d, 4);
        d ^= __shfl_xor_sync(0xffffffffu, d, 2);
        d ^= __shfl_xor_sync(0xffffffffu, d, 1);
        if ((tid & 15) == 0) gxor[tid >> 4] = d;
    }

    __syncthreads();   // barrier 1: hset initialized (gxor fast-path done)

    // ---------------- phase 1: inserts (+ general fallback) ----------------
    if (tid < mc)      hset_insert(hset, hv0);
    if (tid + NT < mc) hset_insert(hset, hv1);

    if (!uniform) {
        for (int s = tid; s < nst && s < MAXST; s += NT) {
            int c = sidx[sbase + s];
            int sze = __ldg(&ZposT[c]);
            int szo = (player == 0) ? __ldg(&ZposT[2 * NN2 + c]) : __ldg(&ZposT[NN2 + c]);
            sdelta[s] = sze ^ szo;
        }
        __syncthreads();
        if (tid < ng) {
            int s0 = sptr[gstart + tid] - sbase;
            int s1 = sptr[gstart + tid + 1] - sbase;
            if (s0 < 0) s0 = 0;
            if (s1 > nst) s1 = nst;
            if (s1 > MAXST) s1 = MAXST;
            int x = 0;
            for (int s = s0; s < s1; ++s) x ^= sdelta[s];
            gxor[tid] = x;
        }
    }

    __syncthreads();   // barrier 2: hset populated, gxor final

    // ---------------- phase 2: candidate + probe + output ----------------
    if (hasc) {
        int cd = 0;
        if (c4.x >= 0) cd ^= gxor[c4.x];
        if (c4.y >= 0) cd ^= gxor[c4.y];
        if (c4.z >= 0) cd ^= gxor[c4.z];
        if (c4.w >= 0) cd ^= gxor[c4.w];
        int pd = ze ^ ((player == 0) ? zb : zw);
        int cand = ch ^ pd ^ cd;

        bool found = false;
        unsigned h = hash_fn(cand) & HASH_MASK;
        while (true) {
            int v = hset[h];
            if (v == -1) break;
            if (v == cand) { found = true; break; }
            h = (h + 1) & HASH_MASK;
        }
        out[(long long)b * NN2 + j] = (lgv != 0 && !found) ? 1.0f : 0.0f;
    }
}

extern "C" void kernel_launch(void* const* d_in, const int* in_sizes, int n_in,
                              void* d_out, int out_size) {
    const int* ZposT        = (const int*)d_in[0];
    const int* cur_player   = (const int*)d_in[1];
    const int* cur_hash     = (const int*)d_in[2];
    const int* hash_hist    = (const int*)d_in[3];
    const int* mv_count     = (const int*)d_in[4];
    const int* lg           = (const int*)d_in[5];
    const int* sidx         = (const int*)d_in[6];
    const int* sptr         = (const int*)d_in[7];
    const int* gptr         = (const int*)d_in[8];
    const int* cap          = (const int*)d_in[9];
    // d_in[10] = scale (unused)

    float* out = (float*)d_out;
    const int B = in_sizes[8] - 1;   // gptr has B+1 entries

    superko_kernel<<<2 * B, NT>>>(ZposT, cur_player, cur_hash, hash_hist,
                                  mv_count, lg, sidx, sptr, gptr, cap, out);
}

// round 9
// speedup vs baseline: 1.5394x; 1.1662x over previous
#include <cuda_runtime.h>
#include <stdint.h>

#define NN2  361
#define MM   361
#define NT   256
#define HASH_SLOTS 1024
#define HASH_MASK  1023
#define MAXG  64
#define MAXST 256

__device__ __forceinline__ unsigned hash_fn(int v) {
    return (((unsigned)v) * 2654435761u) >> 22;   // top 10 bits
}

__device__ __forceinline__ void hset_insert(int* hset, int v) {
    unsigned h = hash_fn(v) & HASH_MASK;
    while (true) {
        int prev = atomicCAS(&hset[h], -1, v);
        if (prev == -1 || prev == v) break;
        h = (h + 1) & HASH_MASK;
    }
}

__device__ __forceinline__ bool hset_probe(const int* hset, int v) {
    unsigned h = hash_fn(v) & HASH_MASK;
    while (true) {
        int s = hset[h];
        if (s == -1) return false;
        if (s == v)  return true;
        h = (h + 1) & HASH_MASK;
    }
}

__global__ __launch_bounds__(NT)
void superko_kernel(const int* __restrict__ ZposT,           // [3, N2]
                    const int* __restrict__ current_player,  // [B]
                    const int* __restrict__ current_hash,    // [B]
                    const int* __restrict__ hash_history,    // [B, M]
                    const int* __restrict__ move_count,      // [B]
                    const int* __restrict__ legal,           // [B, N2] bool(4B)
                    const int* __restrict__ sidx,            // [K]
                    const int* __restrict__ sptr,            // [R+1]
                    const int* __restrict__ gptr,            // [B+1]
                    const int* __restrict__ cap,             // [B, N2, 4]
                    float* __restrict__ out)                 // [B, N2] bool-as-f32
{
    __shared__ int hset[HASH_SLOTS];
    __shared__ int gxor[MAXG];
    __shared__ int sdelta[MAXST];   // general-CSR fallback only

    const int b   = blockIdx.x;
    const int tid = threadIdx.x;

    // -------- phase 0: fire loads --------
    const int player = __ldg(&current_player[b]);
    int mc           = __ldg(&move_count[b]);
    const int ch     = __ldg(&current_hash[b]);
    if (mc > MM) mc = MM;
    if (mc < 0)  mc = 0;

    const int4* cap4 = (const int4*)(cap + (long long)b * NN2 * 4);
    const int*  lg   = legal + (long long)b * NN2;
    const int*  hist = hash_history + (long long)b * MM;

    const int j0 = tid, j1 = tid + NT;
    const bool has1 = (j1 < NN2);

    const int crow = (1 + player) * NN2;   // current player's color row
    const int orow = (2 - player) * NN2;   // opponent's color row

    int4 c4_0 = cap4[j0];
    int  lg_0 = lg[j0];
    int  pd_0 = __ldg(&ZposT[j0]) ^ __ldg(&ZposT[crow + j0]);

    int4 c4_1 = make_int4(-1, -1, -1, -1);
    int  lg_1 = 0, pd_1 = 0;
    if (has1) {
        c4_1 = cap4[j1];
        lg_1 = lg[j1];
        pd_1 = __ldg(&ZposT[j1]) ^ __ldg(&ZposT[crow + j1]);
    }

    int hv0 = hist[j0];
    int hv1 = has1 ? hist[j1] : 0;

    // CSR scalars (broadcast loads)
    const int gstart = gptr[b];
    int ng = gptr[b + 1] - gstart;
    if (ng < 0) ng = 0;
    if (ng > MAXG) ng = MAXG;
    const int sbase = sptr[gstart];
    int nst = sptr[gstart + ng] - sbase;
    if (nst < 0) nst = 0;
    if (nst > MAXST) nst = MAXST;

    bool uniform = (nst == ng * 16) && ((nst & 31) == 0);
    for (int g = 1; g < ng && uniform; ++g)
        uniform = (sptr[gstart + g] == sbase + 16 * g);

    // coalesced stone gather + removal delta
    int sd = 0;
    if (tid < nst) {
        int c = sidx[sbase + tid];
        sd = __ldg(&ZposT[c]) ^ __ldg(&ZposT[orow + c]);
    }

    // hash set init: one STS.128 per thread
    ((int4*)hset)[tid] = make_int4(-1, -1, -1, -1);

    // fast-path group XOR: 16-lane butterfly (no SMEM round trip)
    if (uniform && tid < nst) {
        int d = sd;
        d ^= __shfl_xor_sync(0xffffffffu, d, 8);
        d ^= __shfl_xor_sync(0xffffffffu, d, 4);
        d ^= __shfl_xor_sync(0xffffffffu, d, 2);
        d ^= __shfl_xor_sync(0xffffffffu, d, 1);
        if ((tid & 15) == 0) gxor[tid >> 4] = d;
    }

    __syncthreads();   // barrier 1: hset ready (+ fast-path gxor written)

    // -------- phase 1: inserts --------
    if (tid < mc)      hset_insert(hset, hv0);
    if (tid + NT < mc) hset_insert(hset, hv1);

    if (!uniform) {    // general-CSR fallback (uniform flag identical CTA-wide)
        if (tid < nst) sdelta[tid] = sd;
        __syncthreads();
        if (tid < ng) {
            int s0 = sptr[gstart + tid] - sbase;
            int s1 = sptr[gstart + tid + 1] - sbase;
            if (s0 < 0) s0 = 0;
            if (s1 > nst) s1 = nst;
            int x = 0;
            for (int s = s0; s < s1; ++s) x ^= sdelta[s];
            gxor[tid] = x;
        }
    }

    __syncthreads();   // barrier 2: hset populated, gxor final

    // -------- phase 2: probes (legal-first skip) + output --------
    float* ob = out + (long long)b * NN2;

    {
        float r = 0.0f;
        if (lg_0 != 0) {
            int cd = 0;
            if (c4_0.x >= 0) cd ^= gxor[c4_0.x];
            if (c4_0.y >= 0) cd ^= gxor[c4_0.y];
            if (c4_0.z >= 0) cd ^= gxor[c4_0.z];
            if (c4_0.w >= 0) cd ^= gxor[c4_0.w];
            int cand = ch ^ pd_0 ^ cd;
            r = hset_probe(hset, cand) ? 0.0f : 1.0f;
        }
        ob[j0] = r;
    }
    if (has1) {
        float r = 0.0f;
        if (lg_1 != 0) {
            int cd = 0;
            if (c4_1.x >= 0) cd ^= gxor[c4_1.x];
            if (c4_1.y >= 0) cd ^= gxor[c4_1.y];
            if (c4_1.z >= 0) cd ^= gxor[c4_1.z];
            if (c4_1.w >= 0) cd ^= gxor[c4_1.w];
            int cand = ch ^ pd_1 ^ cd;
            r = hset_probe(hset, cand) ? 0.0f : 1.0f;
        }
        ob[j1] = r;
    }
}

extern "C" void kernel_launch(void* const* d_in, const int* in_sizes, int n_in,
                              void* d_out, int out_size) {
    const int* ZposT        = (const int*)d_in[0];
    const int* cur_player   = (const int*)d_in[1];
    const int* cur_hash     = (const int*)d_in[2];
    const int* hash_hist    = (const int*)d_in[3];
    const int* mv_count     = (const int*)d_in[4];
    const int* lg           = (const int*)d_in[5];
    const int* sidx         = (const int*)d_in[6];
    const int* sptr         = (const int*)d_in[7];
    const int* gptr         = (const int*)d_in[8];
    const int* cap          = (const int*)d_in[9];
    // d_in[10] = scale (unused)

    float* out = (float*)d_out;
    const int B = in_sizes[8] - 1;   // gptr has B+1 entries

    superko_kernel<<<B, NT>>>(ZposT, cur_player, cur_hash, hash_hist,
                              mv_count, lg, sidx, sptr, gptr, cap, out);
}

// round 10
// speedup vs baseline: 1.5714x; 1.0208x over previous
#include <cuda_runtime.h>
#include <stdint.h>

#define NN2  361
#define MM   361
#define NT   512
#define HASH_SLOTS 1024
#define HASH_MASK  1023
#define MAXG  64
#define MAXST 256

__device__ __forceinline__ unsigned hash_fn(int v) {
    return (((unsigned)v) * 2654435761u) >> 22;   // top 10 bits
}

__global__ __launch_bounds__(NT, 4)
void superko_kernel(const int* __restrict__ ZposT,           // [3, N2]
                    const int* __restrict__ current_player,  // [B]
                    const int* __restrict__ current_hash,    // [B]
                    const int* __restrict__ hash_history,    // [B, M]
                    const int* __restrict__ move_count,      // [B]
                    const int* __restrict__ legal,           // [B, N2] bool(4B)
                    const int* __restrict__ sidx,            // [K]
                    const int* __restrict__ sptr,            // [R+1]
                    const int* __restrict__ gptr,            // [B+1]
                    const int* __restrict__ cap,             // [B, N2, 4]
                    float* __restrict__ out)                 // [B, N2] bool-as-f32
{
    __shared__ int hset[HASH_SLOTS];
    __shared__ int gxor[MAXG];
    __shared__ int sdelta[MAXST];   // general-CSR fallback only

    const int b   = blockIdx.x;
    const int tid = threadIdx.x;

    // -------- phase 0: fire loads (one cell / one hist entry / one stone per thread) --------
    const int player = __ldg(&current_player[b]);
    int mc           = __ldg(&move_count[b]);
    const int ch     = __ldg(&current_hash[b]);
    if (mc > MM) mc = MM;
    if (mc < 0)  mc = 0;

    const bool hasc = (tid < NN2);

    const int crow = (1 + player) * NN2;   // current player's color row
    const int orow = (2 - player) * NN2;   // opponent's color row

    int4 c4 = make_int4(-1, -1, -1, -1);
    int  lgv = 0, pd = 0, hv = 0;
    if (hasc) {
        c4  = ((const int4*)(cap + (long long)b * NN2 * 4))[tid];
        lgv = legal[(long long)b * NN2 + tid];
        pd  = __ldg(&ZposT[tid]) ^ __ldg(&ZposT[crow + tid]);
        hv  = hash_history[(long long)b * MM + tid];
    }

    // CSR scalars (broadcast loads)
    const int gstart = gptr[b];
    int ng = gptr[b + 1] - gstart;
    if (ng < 0) ng = 0;
    if (ng > MAXG) ng = MAXG;
    const int sbase = sptr[gstart];
    int nst = sptr[gstart + ng] - sbase;
    if (nst < 0) nst = 0;
    if (nst > MAXST) nst = MAXST;

    bool uniform = (nst == ng * 16) && ((nst & 31) == 0);
    for (int g = 1; g < ng && uniform; ++g)
        uniform = (sptr[gstart + g] == sbase + 16 * g);

    // coalesced stone gather + removal delta (one stone per thread)
    int sd = 0;
    if (tid < nst) {
        int c = sidx[sbase + tid];
        sd = __ldg(&ZposT[c]) ^ __ldg(&ZposT[orow + c]);
    }

    // hash set init: one STS.64 per thread (1024 slots / 512)
    ((int2*)hset)[tid] = make_int2(-1, -1);

    // fast-path group XOR: 16-lane butterfly (full warps: nst multiple of 32)
    if (uniform && tid < nst) {
        int d = sd;
        d ^= __shfl_xor_sync(0xffffffffu, d, 8);
        d ^= __shfl_xor_sync(0xffffffffu, d, 4);
        d ^= __shfl_xor_sync(0xffffffffu, d, 2);
        d ^= __shfl_xor_sync(0xffffffffu, d, 1);
        if ((tid & 15) == 0) gxor[tid >> 4] = d;
    }

    __syncthreads();   // barrier 1: hset ready (+ fast-path gxor written)

    // -------- phase 1: single insert round (mc <= 361 < NT) --------
    if (tid < mc) {
        unsigned h = hash_fn(hv) & HASH_MASK;
        while (true) {
            int prev = atomicCAS(&hset[h], -1, hv);
            if (prev == -1 || prev == hv) break;
            h = (h + 1) & HASH_MASK;
        }
    }

    if (!uniform) {    // general-CSR fallback (flag identical CTA-wide)
        if (tid < nst) sdelta[tid] = sd;
        __syncthreads();
        if (tid < ng) {
            int s0 = sptr[gstart + tid] - sbase;
            int s1 = sptr[gstart + tid + 1] - sbase;
            if (s0 < 0) s0 = 0;
            if (s1 > nst) s1 = nst;
            int x = 0;
            for (int s = s0; s < s1; ++s) x ^= sdelta[s];
            gxor[tid] = x;
        }
    }

    __syncthreads();   // barrier 2: hset populated, gxor final

    // -------- phase 2: probe (legal-first skip) + output --------
    if (hasc) {
        float r = 0.0f;
        if (lgv != 0) {
            int cd = 0;
            if (c4.x >= 0) cd ^= gxor[c4.x];
            if (c4.y >= 0) cd ^= gxor[c4.y];
            if (c4.z >= 0) cd ^= gxor[c4.z];
            if (c4.w >= 0) cd ^= gxor[c4.w];
            int cand = ch ^ pd ^ cd;

            bool found = false;
            unsigned h = hash_fn(cand) & HASH_MASK;
            while (true) {
                int v = hset[h];
                if (v == -1) break;
                if (v == cand) { found = true; break; }
                h = (h + 1) & HASH_MASK;
            }
            r = found ? 0.0f : 1.0f;
        }
        out[(long long)b * NN2 + tid] = r;
    }
}

extern "C" void kernel_launch(void* const* d_in, const int* in_sizes, int n_in,
                              void* d_out, int out_size) {
    const int* ZposT        = (const int*)d_in[0];
    const int* cur_player   = (const int*)d_in[1];
    const int* cur_hash     = (const int*)d_in[2];
    const int* hash_hist    = (const int*)d_in[3];
    const int* mv_count     = (const int*)d_in[4];
    const int* lg           = (const int*)d_in[5];
    const int* sidx         = (const int*)d_in[6];
    const int* sptr         = (const int*)d_in[7];
    const int* gptr         = (const int*)d_in[8];
    const int* cap          = (const int*)d_in[9];
    // d_in[10] = scale (unused)

    float* out = (float*)d_out;
    const int B = in_sizes[8] - 1;   // gptr has B+1 entries

    superko_kernel<<<B, NT>>>(ZposT, cur_player, cur_hash, hash_hist,
                              mv_count, lg, sidx, sptr, gptr, cap, out);
}

// round 11
// speedup vs baseline: 1.5761x; 1.0030x over previous
#include <cuda_runtime.h>
#include <stdint.h>

#define NN2  361
#define MM   361
#define NT   384
#define HASH_SLOTS 1024
#define HASH_MASK  1023
#define MAXG  64
#define MAXST 256

__device__ __forceinline__ unsigned hash_fn(int v) {
    return (((unsigned)v) * 2654435761u) >> 22;   // top 10 bits
}

__global__ __launch_bounds__(NT, 4)
void superko_kernel(const int* __restrict__ ZposT,           // [3, N2]
                    const int* __restrict__ current_player,  // [B]
                    const int* __restrict__ current_hash,    // [B]
                    const int* __restrict__ hash_history,    // [B, M]
                    const int* __restrict__ move_count,      // [B]
                    const int* __restrict__ legal,           // [B, N2] bool(4B)
                    const int* __restrict__ sidx,            // [K]
                    const int* __restrict__ sptr,            // [R+1]
                    const int* __restrict__ gptr,            // [B+1]
                    const int* __restrict__ cap,             // [B, N2, 4]
                    float* __restrict__ out)                 // [B, N2] bool-as-f32
{
    __shared__ int hset[HASH_SLOTS];
    __shared__ int gxor[MAXG];
    __shared__ int sdelta[MAXST];   // general-CSR fallback only
    __shared__ int sflag;           // 1 => uniform 16-stone CSR layout

    const int b   = blockIdx.x;
    const int tid = threadIdx.x;

    // -------- phase 0: fire ALL loads, no player-dependent addressing --------
    const int player = __ldg(&current_player[b]);
    int mc           = __ldg(&move_count[b]);
    const int ch     = __ldg(&current_hash[b]);
    if (mc > MM) mc = MM;
    if (mc < 0)  mc = 0;

    const bool hasc = (tid < NN2);

    int4 c4 = make_int4(-1, -1, -1, -1);
    int  lgv = 0, ze = 0, zb = 0, zw = 0, hv = 0;
    if (hasc) {
        c4  = ((const int4*)(cap + (long long)b * NN2 * 4))[tid];
        lgv = legal[(long long)b * NN2 + tid];
        ze  = __ldg(&ZposT[tid]);
        zb  = __ldg(&ZposT[NN2 + tid]);
        zw  = __ldg(&ZposT[2 * NN2 + tid]);
        hv  = hash_history[(long long)b * MM + tid];
    }

    // CSR scalars (broadcast loads)
    const int gstart = gptr[b];
    int ng = gptr[b + 1] - gstart;
    if (ng < 0) ng = 0;
    if (ng > MAXG) ng = MAXG;
    const int sbase = sptr[gstart];
    int nst = sptr[gstart + ng] - sbase;
    if (nst < 0) nst = 0;
    if (nst > MAXST) nst = MAXST;

    // stone gather, both colors (player-independent)
    int sdb = 0, sdw = 0;
    if (tid < nst) {
        int c   = sidx[sbase + tid];
        int sze = __ldg(&ZposT[c]);
        sdb = sze ^ __ldg(&ZposT[NN2 + c]);       // removal delta if opp = black
        sdw = sze ^ __ldg(&ZposT[2 * NN2 + c]);   // removal delta if opp = white
    }

    // warp 0: PARALLEL uniform-CSR verify (one lane per group boundary)
    if (tid < 32) {
        bool ok = true;
        if (tid == 0)
            ok = (nst == ng * 16) && ((nst & 31) == 0) && (ng <= 31);
        else if (tid <= ng && ng <= 31)
            ok = (sptr[gstart + tid] == sbase + 16 * tid);
        unsigned m = __ballot_sync(0xffffffffu, ok);
        if (tid == 0) sflag = (m == 0xffffffffu) ? 1 : 0;
    }

    // hset init: threads 0-255 do one STS.128 each (4 KB)
    if (tid < 256) ((int4*)hset)[tid] = make_int4(-1, -1, -1, -1);

    // speculative group XOR (overwritten by fallback if layout non-uniform)
    if (tid < nst) {
        int d = (player == 0) ? sdw : sdb;   // opponent = 1 - player
        d ^= __shfl_xor_sync(0xffffffffu, d, 8);
        d ^= __shfl_xor_sync(0xffffffffu, d, 4);
        d ^= __shfl_xor_sync(0xffffffffu, d, 2);
        d ^= __shfl_xor_sync(0xffffffffu, d, 1);
        if ((tid & 15) == 0) gxor[tid >> 4] = d;
    }

    __syncthreads();   // barrier 1: hset ready, sflag + fast-path gxor visible

    // -------- phase 1: single insert round (mc <= 361 < NT) --------
    if (tid < mc) {
        unsigned h = hash_fn(hv) & HASH_MASK;
        while (true) {
            int prev = atomicCAS(&hset[h], -1, hv);
            if (prev == -1 || prev == hv) break;
            h = (h + 1) & HASH_MASK;
        }
    }

    if (!sflag) {      // general-CSR fallback (block-uniform branch)
        if (tid < nst) sdelta[tid] = (player == 0) ? sdw : sdb;
        __syncthreads();
        if (tid < ng) {
            int s0 = sptr[gstart + tid] - sbase;
            int s1 = sptr[gstart + tid + 1] - sbase;
            if (s0 < 0) s0 = 0;
            if (s1 > nst) s1 = nst;
            int x = 0;
            for (int s = s0; s < s1; ++s) x ^= sdelta[s];
            gxor[tid] = x;
        }
    }

    __syncthreads();   // barrier 2: hset populated, gxor final

    // -------- phase 2: probe (legal-first skip) + output --------
    if (hasc) {
        float r = 0.0f;
        if (lgv != 0) {
            int cd = 0;
            if (c4.x >= 0) cd ^= gxor[c4.x];
            if (c4.y >= 0) cd ^= gxor[c4.y];
            if (c4.z >= 0) cd ^= gxor[c4.z];
            if (c4.w >= 0) cd ^= gxor[c4.w];
            int pd = ze ^ ((player == 0) ? zb : zw);
            int cand = ch ^ pd ^ cd;

            bool found = false;
            unsigned h = hash_fn(cand) & HASH_MASK;
            while (true) {
                int v = hset[h];
                if (v == -1) break;
                if (v == cand) { found = true; break; }
                h = (h + 1) & HASH_MASK;
            }
            r = found ? 0.0f : 1.0f;
        }
        out[(long long)b * NN2 + tid] = r;
    }
}

extern "C" void kernel_launch(void* const* d_in, const int* in_sizes, int n_in,
                              void* d_out, int out_size) {
    const int* ZposT        = (const int*)d_in[0];
    const int* cur_player   = (const int*)d_in[1];
    const int* cur_hash     = (const int*)d_in[2];
    const int* hash_hist    = (const int*)d_in[3];
    const int* mv_count     = (const int*)d_in[4];
    const int* lg           = (const int*)d_in[5];
    const int* sidx         = (const int*)d_in[6];
    const int* sptr         = (const int*)d_in[7];
    const int* gptr         = (const int*)d_in[8];
    const int* cap          = (const int*)d_in[9];
    // d_in[10] = scale (unused)

    float* out = (float*)d_out;
    const int B = in_sizes[8] - 1;   // gptr has B+1 entries

    superko_kernel<<<B, NT>>>(ZposT, cur_player, cur_hash, hash_hist,
                              mv_count, lg, sidx, sptr, gptr, cap, out);
}